// round 9
// baseline (speedup 1.0000x reference)
#include <cuda_runtime.h>
#include <cuda_bf16.h>
#include <cstdint>

#define D_      256
#define MROWS   128
#define TCODES  64
#define THREADS 256

#define MAXN 65536
#define MAXK 4096
#define TILE_BYTES 33024      // 64 codes x 512B swizzled + 64 floats enorm + pad

// ---------------- static device scratch ----------------
__device__ __align__(128) unsigned char g_cbt[(MAXK / TCODES) * TILE_BYTES];
__device__ float  g_enorm[MAXK];
__device__ float  g_zn[MAXN];
__device__ int4   g_cand[MAXN];
__device__ double g_partial[MAXN / 8];

// ---------------- smem layout (bytes) ----------------
#define OFF_A    0u          // 128 rows x 512B (hi only, swizzled)
#define OFF_B0   65536u      // 33024B tile image (codes + enorm)
#define OFF_B1   98560u
#define OFF_ZNF  131584u     // 128 floats
#define OFF_MBAR 132096u     // 2 x 8B mbarrier
#define SMEM_TOTAL 132352

// ---------------- helpers ----------------
__device__ __forceinline__ uint32_t smem_u32(const void* p) {
    uint32_t a;
    asm("{ .reg .u64 t; cvta.to.shared.u64 t, %1; cvt.u32.u64 %0, t; }" : "=r"(a) : "l"(p));
    return a;
}
__device__ __forceinline__ void ldsm4(uint32_t* r, uint32_t addr) {
    asm volatile("ldmatrix.sync.aligned.m8n8.x4.shared.b16 {%0,%1,%2,%3}, [%4];"
        : "=r"(r[0]), "=r"(r[1]), "=r"(r[2]), "=r"(r[3]) : "r"(addr));
}
__device__ __forceinline__ void mma16816(float* c, const uint32_t* a, uint32_t b0, uint32_t b1) {
    asm volatile("mma.sync.aligned.m16n8k16.row.col.f32.bf16.bf16.f32 "
        "{%0,%1,%2,%3}, {%4,%5,%6,%7}, {%8,%9}, {%0,%1,%2,%3};"
        : "+f"(c[0]), "+f"(c[1]), "+f"(c[2]), "+f"(c[3])
        : "r"(a[0]), "r"(a[1]), "r"(a[2]), "r"(a[3]), "r"(b0), "r"(b1));
}
__device__ __forceinline__ uint4 conv8hi(const float4 v0, const float4 v1) {
    float f[8] = {v0.x, v0.y, v0.z, v0.w, v1.x, v1.y, v1.z, v1.w};
    uint32_t h[4];
    #pragma unroll
    for (int i = 0; i < 4; i++) {
        __nv_bfloat162 hp;
        hp.x = __float2bfloat16(f[2*i]);
        hp.y = __float2bfloat16(f[2*i+1]);
        h[i] = *(uint32_t*)&hp;
    }
    return make_uint4(h[0], h[1], h[2], h[3]);
}

#define MBARRIER_INIT(mbar, cnt) \
    asm volatile("mbarrier.init.shared.b64 [%0], %1;" :: "r"((uint32_t)(mbar)), "r"((uint32_t)(cnt)) : "memory")
#define MBARRIER_EXPECT_TX(mbar, bytes) \
    asm volatile("mbarrier.arrive.expect_tx.shared.b64 _, [%0], %1;" \
                 :: "r"((uint32_t)(mbar)), "r"((uint32_t)(bytes)) : "memory")
#define BULK_G2S(dst, src, bytes, mbar) \
    asm volatile("cp.async.bulk.shared::cta.global.mbarrier::complete_tx::bytes [%0], [%1], %2, [%3];" \
                 :: "r"((uint32_t)(dst)), "l"(src), "r"((uint32_t)(bytes)), "r"((uint32_t)(mbar)) : "memory")
#define WAITP(mbar, par) do { \
    uint32_t _m = (uint32_t)(mbar); uint32_t _p = (uint32_t)(par); uint32_t _d; \
    asm volatile("{\n\t.reg .pred p;\n\t" \
        "mbarrier.try_wait.parity.acquire.cta.shared::cta.b64 p, [%1], %2;\n\t" \
        "selp.b32 %0, 1, 0, p;\n\t}" : "=r"(_d) : "r"(_m), "r"(_p) : "memory"); \
    if (!_d) { \
        asm volatile("{\n\t.reg .pred P1;\n\t" \
            "WL_%=:\n\t" \
            "mbarrier.try_wait.parity.acquire.cta.shared::cta.b64 P1, [%0], %1, 0x989680;\n\t" \
            "@P1 bra.uni WD_%=;\n\t" \
            "bra.uni WL_%=;\n\t" \
            "WD_%=:\n\t}" :: "r"(_m), "r"(_p) : "memory"); \
    } } while (0)

// strict-< insertion into sorted-4 (ties keep existing entry = earlier index,
// valid because each thread scans its codes in ascending index order)
#define UPD4(bv, bi, d, ix) do { \
    if ((d) < bv[3]) { \
        if ((d) < bv[1]) { \
            bv[3] = bv[2]; bi[3] = bi[2]; bv[2] = bv[1]; bi[2] = bi[1]; \
            if ((d) < bv[0]) { bv[1] = bv[0]; bi[1] = bi[0]; bv[0] = (d); bi[0] = (ix); } \
            else             { bv[1] = (d); bi[1] = (ix); } \
        } else { \
            if ((d) < bv[2]) { bv[3] = bv[2]; bi[3] = bi[2]; bv[2] = (d); bi[2] = (ix); } \
            else             { bv[3] = (d); bi[3] = (ix); } \
        } \
    } } while (0)

// lexicographic (value, index) insertion — used when merging other lanes' lists
__device__ __forceinline__ void ins4(float* bv, int* bi, float v, int ix) {
    bool b3 = (v < bv[3]) || (v == bv[3] && ix < bi[3]);
    if (!b3) return;
    bool b2 = (v < bv[2]) || (v == bv[2] && ix < bi[2]);
    bool b1 = (v < bv[1]) || (v == bv[1] && ix < bi[1]);
    bool b0 = (v < bv[0]) || (v == bv[0] && ix < bi[0]);
    int p = 3;
    if (b2) { bv[3] = bv[2]; bi[3] = bi[2]; p = 2;
        if (b1) { bv[2] = bv[1]; bi[2] = bi[1]; p = 1;
            if (b0) { bv[1] = bv[0]; bi[1] = bi[0]; p = 0; } } }
    bv[p] = v; bi[p] = ix;
}

// ---------------- kernel 0: codebook -> pre-swizzled bf16 tile images + norms ----------------
__global__ void vq_prep(const float* __restrict__ cb, int K) {
    int c = blockIdx.x * (blockDim.x >> 5) + (threadIdx.x >> 5);
    int lane = threadIdx.x & 31;
    if (c >= K) return;
    const float4* row = (const float4*)(cb + (size_t)c * D_);
    float4 v0 = row[lane * 2], v1 = row[lane * 2 + 1];
    uint4 h = conv8hi(v0, v1);

    int t = c >> 6, r = c & 63;
    unsigned char* blk = g_cbt + (size_t)t * TILE_BYTES;
    *(uint4*)(blk + r * 512 + ((lane ^ (r & 7)) << 4)) = h;

    double s = (double)v0.x * v0.x + (double)v0.y * v0.y + (double)v0.z * v0.z + (double)v0.w * v0.w
             + (double)v1.x * v1.x + (double)v1.y * v1.y + (double)v1.z * v1.z + (double)v1.w * v1.w;
    for (int o = 16; o; o >>= 1) s += __shfl_xor_sync(0xFFFFFFFFu, s, o);
    if (lane == 0) {
        float en = (float)s;
        *(float*)(blk + 32768 + r * 4) = en;
        g_enorm[c] = en;
    }
}

// ---------------- main kernel: HMMA distance GEMM + fused top-4 argmin ----------------
__global__ void __launch_bounds__(THREADS, 1)
vq_tc(const float* __restrict__ z, int K)
{
    extern __shared__ char smc[];
    const uint32_t sb = smem_u32(smc);
    const int tid  = threadIdx.x;
    const int warp = tid >> 5;
    const int lane = tid & 31;
    const int R0   = blockIdx.x * MROWS;
    const int TILES = K / TCODES;     // 64

    // ---- init mbarriers, kick off first two tile bulk loads ----
    if (tid == 0) {
        MBARRIER_INIT(sb + OFF_MBAR + 0, 1);
        MBARRIER_INIT(sb + OFF_MBAR + 8, 1);
    }
    __syncthreads();
    if (tid == 0) {
        MBARRIER_EXPECT_TX(sb + OFF_MBAR + 0, TILE_BYTES);
        BULK_G2S(sb + OFF_B0, g_cbt, TILE_BYTES, sb + OFF_MBAR + 0);
        MBARRIER_EXPECT_TX(sb + OFF_MBAR + 8, TILE_BYTES);
        BULK_G2S(sb + OFF_B1, g_cbt + TILE_BYTES, TILE_BYTES, sb + OFF_MBAR + 8);
    }

    // ---- A prologue: z rows -> hi bf16 in smem (swizzled) ----
    #pragma unroll 1
    for (int i = 0; i < 16; i++) {
        int u = tid + i * THREADS;                 // 0..4095
        int r = u >> 5, c8 = u & 31;               // row, 8-elem chunk
        const float4* p = (const float4*)(z + (size_t)(R0 + r) * D_ + c8 * 8);
        uint4 hi = conv8hi(p[0], p[1]);
        int sw = c8 ^ (r & 7);
        *(uint4*)(smc + OFF_A + r * 512 + (sw << 4)) = hi;
    }

    // ---- z row norms (double accumulation, correctly rounded) ----
    float* znf = (float*)(smc + OFF_ZNF);
    if (tid < MROWS) {
        const float4* zr = (const float4*)(z + (size_t)(R0 + tid) * D_);
        double s = 0.0;
        #pragma unroll 8
        for (int i = 0; i < 64; i++) {
            float4 v = zr[i];
            s += (double)v.x * v.x + (double)v.y * v.y + (double)v.z * v.z + (double)v.w * v.w;
        }
        float zv = (float)s;
        znf[tid] = zv;
        g_zn[R0 + tid] = zv;
    }
    __syncthreads();

    const int rowA = warp * 16 + (lane >> 2);
    const int col0 = (lane & 3) * 2;
    const float znA = znf[rowA];
    const float znB = znf[rowA + 8];

    const uint32_t aBase = sb + OFF_A + (uint32_t)(warp * 16 + (lane & 15)) * 512;
    const uint32_t aXor  = (uint32_t)(lane & 7);
    const int      aSel  = lane >> 4;
    const int      bSel  = lane >> 3;

    float bvA[4], bvB[4];
    int   biA[4], biB[4];
    #pragma unroll
    for (int i = 0; i < 4; i++) {
        bvA[i] = __int_as_float(0x7f800000); bvB[i] = bvA[i];
        biA[i] = 0x3fffffff; biB[i] = 0x3fffffff;
    }

    for (int t = 0; t < TILES; t++) {
        const uint32_t buf = (t & 1) ? OFF_B1 : OFF_B0;
        WAITP(sb + OFF_MBAR + (t & 1) * 8, (t >> 1) & 1);

        const float*   enp   = (const float*)(smc + buf + 32768);
        const uint32_t bBase = sb + buf + (uint32_t)(lane & 7) * 512;

        float c[8][4];
        #pragma unroll
        for (int j = 0; j < 8; j++)
            #pragma unroll
            for (int q = 0; q < 4; q++) c[j][q] = 0.0f;

        #pragma unroll
        for (int kk2 = 0; kk2 < 8; kk2++) {
            uint32_t ah0[4], ah1[4];
            int kc0 = 4 * kk2 + aSel;
            int kc1 = kc0 + 2;
            ldsm4(ah0, aBase + (uint32_t)((kc0 ^ aXor) << 4));
            ldsm4(ah1, aBase + (uint32_t)((kc1 ^ aXor) << 4));
            uint32_t b[8][4];
            int bc = (4 * kk2 + bSel) ^ aXor;
            #pragma unroll
            for (int j = 0; j < 8; j++)
                ldsm4(b[j], bBase + (uint32_t)(j * 4096) + (uint32_t)(bc << 4));
            #pragma unroll
            for (int j = 0; j < 8; j++) {
                mma16816(c[j], ah0, b[j][0], b[j][1]);
                mma16816(c[j], ah1, b[j][2], b[j][3]);
            }
        }

        // ---- fused epilogue: dist + per-thread top-4 ----
        #pragma unroll
        for (int j = 0; j < 8; j++) {
            int cb = t * TCODES + j * 8 + col0;
            float en0 = enp[j * 8 + col0];
            float en1 = enp[j * 8 + col0 + 1];
            float d;
            d = __fmaf_rn(-2.0f, c[j][0], __fadd_rn(znA, en0)); UPD4(bvA, biA, d, cb);
            d = __fmaf_rn(-2.0f, c[j][1], __fadd_rn(znA, en1)); UPD4(bvA, biA, d, cb + 1);
            d = __fmaf_rn(-2.0f, c[j][2], __fadd_rn(znB, en0)); UPD4(bvB, biB, d, cb);
            d = __fmaf_rn(-2.0f, c[j][3], __fadd_rn(znB, en1)); UPD4(bvB, biB, d, cb + 1);
        }
        __syncthreads();   // all threads done reading buffer (t&1)

        if (tid == 0 && t + 2 < TILES) {
            MBARRIER_EXPECT_TX(sb + OFF_MBAR + (t & 1) * 8, TILE_BYTES);
            BULK_G2S(sb + buf, g_cbt + (size_t)(t + 2) * TILE_BYTES,
                     TILE_BYTES, sb + OFF_MBAR + (t & 1) * 8);
        }
    }

    // ---- merge top-4 across the 4 lanes sharing each row ----
    #pragma unroll
    for (int off = 1; off < 4; off <<= 1) {
        float ov[4]; int oi[4];
        #pragma unroll
        for (int s = 0; s < 4; s++) {
            ov[s] = __shfl_xor_sync(0xFFFFFFFFu, bvA[s], off, 4);
            oi[s] = __shfl_xor_sync(0xFFFFFFFFu, biA[s], off, 4);
        }
        #pragma unroll
        for (int s = 0; s < 4; s++) ins4(bvA, biA, ov[s], oi[s]);
        #pragma unroll
        for (int s = 0; s < 4; s++) {
            ov[s] = __shfl_xor_sync(0xFFFFFFFFu, bvB[s], off, 4);
            oi[s] = __shfl_xor_sync(0xFFFFFFFFu, biB[s], off, 4);
        }
        #pragma unroll
        for (int s = 0; s < 4; s++) ins4(bvB, biB, ov[s], oi[s]);
    }
    if ((lane & 3) == 0) {
        g_cand[R0 + rowA]     = make_int4(biA[0], biA[1], biA[2], biA[3]);
        g_cand[R0 + rowA + 8] = make_int4(biB[0], biB[1], biB[2], biB[3]);
    }
}

// ---------------- rescore: exact fp32 decision among top-4 + per-block loss ----------------
__global__ void vq_rescore(const float* __restrict__ z, const float* __restrict__ cb,
                           float* __restrict__ out_zq, float* __restrict__ out_idx_f,
                           int writeIdx, int N)
{
    __shared__ double sred[8];
    int wIn = threadIdx.x >> 5;
    int gw = blockIdx.x * 8 + wIn;
    int lane = threadIdx.x & 31;

    double ls = 0.0;
    if (gw < N) {
        int4 cand = g_cand[gw];
        int ci[4] = {cand.x, cand.y, cand.z, cand.w};
        float zn = g_zn[gw];

        const float4* zr = (const float4*)(z + (size_t)gw * D_);
        float4 za = zr[lane * 2], zb = zr[lane * 2 + 1];

        float4 ea[4], eb[4];
        float dot[4];
        #pragma unroll
        for (int q = 0; q < 4; q++) {
            const float4* ep = (const float4*)(cb + (size_t)ci[q] * D_);
            ea[q] = ep[lane * 2]; eb[q] = ep[lane * 2 + 1];
            dot[q] = za.x * ea[q].x + za.y * ea[q].y + za.z * ea[q].z + za.w * ea[q].w
                   + zb.x * eb[q].x + zb.y * eb[q].y + zb.z * eb[q].z + zb.w * eb[q].w;
        }
        #pragma unroll
        for (int o = 16; o; o >>= 1)
            #pragma unroll
            for (int q = 0; q < 4; q++)
                dot[q] += __shfl_xor_sync(0xFFFFFFFFu, dot[q], o);

        float bd = __int_as_float(0x7f800000);
        int   bi = 0x7fffffff, bq = 0;
        #pragma unroll
        for (int q = 0; q < 4; q++) {
            float dist = __fmaf_rn(-2.0f, dot[q], __fadd_rn(zn, g_enorm[ci[q]]));
            if (dist < bd || (dist == bd && ci[q] < bi)) { bd = dist; bi = ci[q]; bq = q; }
        }

        float4 wa = ea[bq], wb = eb[bq];
        float4* outr = (float4*)(out_zq + (size_t)gw * D_);
        outr[lane * 2]     = wa;
        outr[lane * 2 + 1] = wb;

        double dx;
        dx = (double)wa.x - za.x; ls += dx * dx;
        dx = (double)wa.y - za.y; ls += dx * dx;
        dx = (double)wa.z - za.z; ls += dx * dx;
        dx = (double)wa.w - za.w; ls += dx * dx;
        dx = (double)wb.x - zb.x; ls += dx * dx;
        dx = (double)wb.y - zb.y; ls += dx * dx;
        dx = (double)wb.z - zb.z; ls += dx * dx;
        dx = (double)wb.w - zb.w; ls += dx * dx;
        for (int o = 16; o; o >>= 1) ls += __shfl_xor_sync(0xFFFFFFFFu, ls, o);
        if (lane == 0 && writeIdx) out_idx_f[gw] = (float)bi;
    }
    if (lane == 0) sred[wIn] = ls;
    __syncthreads();
    if (threadIdx.x == 0) {
        double s = 0.0;
        #pragma unroll
        for (int w = 0; w < 8; w++) s += sred[w];
        g_partial[blockIdx.x] = s;
    }
}

// ---------------- deterministic loss reduction ----------------
__global__ void vq_loss(float* out_loss, int nPart, long long nElem) {
    __shared__ double s[256];
    double a0 = 0.0, a1 = 0.0, a2 = 0.0, a3 = 0.0;
    for (int i = threadIdx.x * 4; i < nPart; i += 1024) {
        a0 += g_partial[i]; a1 += g_partial[i + 1];
        a2 += g_partial[i + 2]; a3 += g_partial[i + 3];
    }
    s[threadIdx.x] = (a0 + a1) + (a2 + a3);
    __syncthreads();
    #pragma unroll
    for (int k = 128; k > 0; k >>= 1) {
        if (threadIdx.x < k) s[threadIdx.x] += s[threadIdx.x + k];
        __syncthreads();
    }
    if (threadIdx.x == 0)
        *out_loss = (float)(0.25 * s[0] / (double)nElem);
}

extern "C" void kernel_launch(void* const* d_in, const int* in_sizes, int n_in,
                              void* d_out, int out_size)
{
    const float* z  = (const float*)d_in[0];
    const float* cb = (const float*)d_in[1];
    const int N = in_sizes[0] / D_;
    const int K = in_sizes[1] / D_;

    float* out = (float*)d_out;
    const long long zq = (long long)N * D_;
    float* out_idx = nullptr;
    float* out_loss = nullptr;
    int writeIdx = 0;
    long long osz = (long long)out_size;
    if (osz >= zq + N) { out_idx = out + zq; writeIdx = 1; }
    if (osz >= zq + N + 1) out_loss = out + zq + N;
    else if (osz == zq + 1) out_loss = out + zq;

    cudaFuncSetAttribute(vq_tc, cudaFuncAttributeMaxDynamicSharedMemorySize, SMEM_TOTAL);

    vq_prep<<<(K + 7) / 8, 256>>>(cb, K);
    vq_tc<<<N / MROWS, THREADS, SMEM_TOTAL>>>(z, K);
    vq_rescore<<<N / 8, 256>>>(z, cb, out, out_idx, writeIdx, N);
    if (out_loss) vq_loss<<<1, 256>>>(out_loss, N / 8, (long long)N * D_);
}

// round 10
// speedup vs baseline: 1.0017x; 1.0017x over previous
#include <cuda_runtime.h>
#include <cuda_bf16.h>
#include <cstdint>

#define D_      256
#define MROWS   128
#define TCODES  64
#define THREADS 256

#define MAXN 65536
#define MAXK 4096
#define TILE_BYTES 33024      // 64 codes x 512B swizzled + 64 floats enorm + pad

// ---------------- static device scratch ----------------
__device__ __align__(128) unsigned char g_cbt[(MAXK / TCODES) * TILE_BYTES];
__device__ float  g_enorm[MAXK];
__device__ float  g_zn[MAXN];
__device__ int4   g_cand[MAXN];
__device__ double g_partial[MAXN / 8];

// ---------------- smem layout (bytes) ----------------
#define OFF_A    0u          // 128 rows x 512B (hi only, swizzled)
#define OFF_B0   65536u      // 33024B tile image (codes + enorm)
#define OFF_B1   98560u
#define OFF_ZNF  131584u     // 128 floats
#define OFF_MBAR 132096u     // 2 x 8B mbarrier
#define SMEM_TOTAL 132352

// ---------------- helpers ----------------
__device__ __forceinline__ uint32_t smem_u32(const void* p) {
    uint32_t a;
    asm("{ .reg .u64 t; cvta.to.shared.u64 t, %1; cvt.u32.u64 %0, t; }" : "=r"(a) : "l"(p));
    return a;
}
__device__ __forceinline__ void ldsm4(uint32_t* r, uint32_t addr) {
    asm volatile("ldmatrix.sync.aligned.m8n8.x4.shared.b16 {%0,%1,%2,%3}, [%4];"
        : "=r"(r[0]), "=r"(r[1]), "=r"(r[2]), "=r"(r[3]) : "r"(addr));
}
__device__ __forceinline__ void mma16816(float* c, const uint32_t* a, uint32_t b0, uint32_t b1) {
    asm volatile("mma.sync.aligned.m16n8k16.row.col.f32.bf16.bf16.f32 "
        "{%0,%1,%2,%3}, {%4,%5,%6,%7}, {%8,%9}, {%0,%1,%2,%3};"
        : "+f"(c[0]), "+f"(c[1]), "+f"(c[2]), "+f"(c[3])
        : "r"(a[0]), "r"(a[1]), "r"(a[2]), "r"(a[3]), "r"(b0), "r"(b1));
}
__device__ __forceinline__ uint4 conv8hi(const float4 v0, const float4 v1) {
    float f[8] = {v0.x, v0.y, v0.z, v0.w, v1.x, v1.y, v1.z, v1.w};
    uint32_t h[4];
    #pragma unroll
    for (int i = 0; i < 4; i++) {
        __nv_bfloat162 hp;
        hp.x = __float2bfloat16(f[2*i]);
        hp.y = __float2bfloat16(f[2*i+1]);
        h[i] = *(uint32_t*)&hp;
    }
    return make_uint4(h[0], h[1], h[2], h[3]);
}

#define MBARRIER_INIT(mbar, cnt) \
    asm volatile("mbarrier.init.shared.b64 [%0], %1;" :: "r"((uint32_t)(mbar)), "r"((uint32_t)(cnt)) : "memory")
#define MBARRIER_EXPECT_TX(mbar, bytes) \
    asm volatile("mbarrier.arrive.expect_tx.shared.b64 _, [%0], %1;" \
                 :: "r"((uint32_t)(mbar)), "r"((uint32_t)(bytes)) : "memory")
#define BULK_G2S(dst, src, bytes, mbar) \
    asm volatile("cp.async.bulk.shared::cta.global.mbarrier::complete_tx::bytes [%0], [%1], %2, [%3];" \
                 :: "r"((uint32_t)(dst)), "l"(src), "r"((uint32_t)(bytes)), "r"((uint32_t)(mbar)) : "memory")
#define WAITP(mbar, par) do { \
    uint32_t _m = (uint32_t)(mbar); uint32_t _p = (uint32_t)(par); uint32_t _d; \
    asm volatile("{\n\t.reg .pred p;\n\t" \
        "mbarrier.try_wait.parity.acquire.cta.shared::cta.b64 p, [%1], %2;\n\t" \
        "selp.b32 %0, 1, 0, p;\n\t}" : "=r"(_d) : "r"(_m), "r"(_p) : "memory"); \
    if (!_d) { \
        asm volatile("{\n\t.reg .pred P1;\n\t" \
            "WL_%=:\n\t" \
            "mbarrier.try_wait.parity.acquire.cta.shared::cta.b64 P1, [%0], %1, 0x989680;\n\t" \
            "@P1 bra.uni WD_%=;\n\t" \
            "bra.uni WL_%=;\n\t" \
            "WD_%=:\n\t}" :: "r"(_m), "r"(_p) : "memory"); \
    } } while (0)

// strict-< insertion into sorted-4 (ties keep existing entry = earlier index,
// valid because each thread scans its codes in ascending index order)
#define UPD4(bv, bi, d, ix) do { \
    if ((d) < bv[3]) { \
        if ((d) < bv[1]) { \
            bv[3] = bv[2]; bi[3] = bi[2]; bv[2] = bv[1]; bi[2] = bi[1]; \
            if ((d) < bv[0]) { bv[1] = bv[0]; bi[1] = bi[0]; bv[0] = (d); bi[0] = (ix); } \
            else             { bv[1] = (d); bi[1] = (ix); } \
        } else { \
            if ((d) < bv[2]) { bv[3] = bv[2]; bi[3] = bi[2]; bv[2] = (d); bi[2] = (ix); } \
            else             { bv[3] = (d); bi[3] = (ix); } \
        } \
    } } while (0)

// lexicographic (value, index) insertion — used when merging other lanes' lists
__device__ __forceinline__ void ins4(float* bv, int* bi, float v, int ix) {
    bool b3 = (v < bv[3]) || (v == bv[3] && ix < bi[3]);
    if (!b3) return;
    bool b2 = (v < bv[2]) || (v == bv[2] && ix < bi[2]);
    bool b1 = (v < bv[1]) || (v == bv[1] && ix < bi[1]);
    bool b0 = (v < bv[0]) || (v == bv[0] && ix < bi[0]);
    int p = 3;
    if (b2) { bv[3] = bv[2]; bi[3] = bi[2]; p = 2;
        if (b1) { bv[2] = bv[1]; bi[2] = bi[1]; p = 1;
            if (b0) { bv[1] = bv[0]; bi[1] = bi[0]; p = 0; } } }
    bv[p] = v; bi[p] = ix;
}

// ---------------- kernel 0: codebook -> pre-swizzled bf16 tile images + norms ----------------
__global__ void vq_prep(const float* __restrict__ cb, int K) {
    int c = blockIdx.x * (blockDim.x >> 5) + (threadIdx.x >> 5);
    int lane = threadIdx.x & 31;
    if (c >= K) return;
    const float4* row = (const float4*)(cb + (size_t)c * D_);
    float4 v0 = row[lane * 2], v1 = row[lane * 2 + 1];
    uint4 h = conv8hi(v0, v1);

    int t = c >> 6, r = c & 63;
    unsigned char* blk = g_cbt + (size_t)t * TILE_BYTES;
    *(uint4*)(blk + r * 512 + ((lane ^ (r & 7)) << 4)) = h;

    double s = (double)v0.x * v0.x + (double)v0.y * v0.y + (double)v0.z * v0.z + (double)v0.w * v0.w
             + (double)v1.x * v1.x + (double)v1.y * v1.y + (double)v1.z * v1.z + (double)v1.w * v1.w;
    for (int o = 16; o; o >>= 1) s += __shfl_xor_sync(0xFFFFFFFFu, s, o);
    if (lane == 0) {
        float en = (float)s;
        *(float*)(blk + 32768 + r * 4) = en;
        g_enorm[c] = en;
    }
}

// ---------------- main kernel: HMMA distance GEMM + fused top-4 argmin ----------------
__global__ void __launch_bounds__(THREADS, 1)
vq_tc(const float* __restrict__ z, int K)
{
    extern __shared__ char smc[];
    const uint32_t sb = smem_u32(smc);
    const int tid  = threadIdx.x;
    const int warp = tid >> 5;
    const int lane = tid & 31;
    const int R0   = blockIdx.x * MROWS;
    const int TILES = K / TCODES;     // 64

    // ---- init mbarriers, kick off first two tile bulk loads ----
    if (tid == 0) {
        MBARRIER_INIT(sb + OFF_MBAR + 0, 1);
        MBARRIER_INIT(sb + OFF_MBAR + 8, 1);
    }
    __syncthreads();
    if (tid == 0) {
        MBARRIER_EXPECT_TX(sb + OFF_MBAR + 0, TILE_BYTES);
        BULK_G2S(sb + OFF_B0, g_cbt, TILE_BYTES, sb + OFF_MBAR + 0);
        MBARRIER_EXPECT_TX(sb + OFF_MBAR + 8, TILE_BYTES);
        BULK_G2S(sb + OFF_B1, g_cbt + TILE_BYTES, TILE_BYTES, sb + OFF_MBAR + 8);
    }

    // ---- A prologue: z rows -> hi bf16 in smem (swizzled) ----
    #pragma unroll 1
    for (int i = 0; i < 16; i++) {
        int u = tid + i * THREADS;                 // 0..4095
        int r = u >> 5, c8 = u & 31;               // row, 8-elem chunk
        const float4* p = (const float4*)(z + (size_t)(R0 + r) * D_ + c8 * 8);
        uint4 hi = conv8hi(p[0], p[1]);
        int sw = c8 ^ (r & 7);
        *(uint4*)(smc + OFF_A + r * 512 + (sw << 4)) = hi;
    }

    // ---- z row norms (double accumulation, correctly rounded) ----
    float* znf = (float*)(smc + OFF_ZNF);
    if (tid < MROWS) {
        const float4* zr = (const float4*)(z + (size_t)(R0 + tid) * D_);
        double s = 0.0;
        #pragma unroll 8
        for (int i = 0; i < 64; i++) {
            float4 v = zr[i];
            s += (double)v.x * v.x + (double)v.y * v.y + (double)v.z * v.z + (double)v.w * v.w;
        }
        float zv = (float)s;
        znf[tid] = zv;
        g_zn[R0 + tid] = zv;
    }
    __syncthreads();

    const int rowA = warp * 16 + (lane >> 2);
    const int col0 = (lane & 3) * 2;
    const float znA = znf[rowA];
    const float znB = znf[rowA + 8];

    const uint32_t aBase = sb + OFF_A + (uint32_t)(warp * 16 + (lane & 15)) * 512;
    const uint32_t aXor  = (uint32_t)(lane & 7);
    const int      aSel  = lane >> 4;
    const int      bSel  = lane >> 3;

    float bvA[4], bvB[4];
    int   biA[4], biB[4];
    #pragma unroll
    for (int i = 0; i < 4; i++) {
        bvA[i] = __int_as_float(0x7f800000); bvB[i] = bvA[i];
        biA[i] = 0x3fffffff; biB[i] = 0x3fffffff;
    }

    for (int t = 0; t < TILES; t++) {
        const uint32_t buf = (t & 1) ? OFF_B1 : OFF_B0;
        WAITP(sb + OFF_MBAR + (t & 1) * 8, (t >> 1) & 1);

        const float*   enp   = (const float*)(smc + buf + 32768);
        const uint32_t bBase = sb + buf + (uint32_t)(lane & 7) * 512;

        float c[8][4];
        #pragma unroll
        for (int j = 0; j < 8; j++)
            #pragma unroll
            for (int q = 0; q < 4; q++) c[j][q] = 0.0f;

        #pragma unroll
        for (int kk2 = 0; kk2 < 8; kk2++) {
            uint32_t ah0[4], ah1[4];
            int kc0 = 4 * kk2 + aSel;
            int kc1 = kc0 + 2;
            ldsm4(ah0, aBase + (uint32_t)((kc0 ^ aXor) << 4));
            ldsm4(ah1, aBase + (uint32_t)((kc1 ^ aXor) << 4));
            uint32_t b[8][4];
            int bc = (4 * kk2 + bSel) ^ aXor;
            #pragma unroll
            for (int j = 0; j < 8; j++)
                ldsm4(b[j], bBase + (uint32_t)(j * 4096) + (uint32_t)(bc << 4));
            #pragma unroll
            for (int j = 0; j < 8; j++) {
                mma16816(c[j], ah0, b[j][0], b[j][1]);
                mma16816(c[j], ah1, b[j][2], b[j][3]);
            }
        }

        // ---- fused epilogue: dist + per-thread top-4 ----
        #pragma unroll
        for (int j = 0; j < 8; j++) {
            int cb = t * TCODES + j * 8 + col0;
            float en0 = enp[j * 8 + col0];
            float en1 = enp[j * 8 + col0 + 1];
            float d;
            d = __fmaf_rn(-2.0f, c[j][0], __fadd_rn(znA, en0)); UPD4(bvA, biA, d, cb);
            d = __fmaf_rn(-2.0f, c[j][1], __fadd_rn(znA, en1)); UPD4(bvA, biA, d, cb + 1);
            d = __fmaf_rn(-2.0f, c[j][2], __fadd_rn(znB, en0)); UPD4(bvB, biB, d, cb);
            d = __fmaf_rn(-2.0f, c[j][3], __fadd_rn(znB, en1)); UPD4(bvB, biB, d, cb + 1);
        }
        __syncthreads();   // all threads done reading buffer (t&1)

        if (tid == 0 && t + 2 < TILES) {
            MBARRIER_EXPECT_TX(sb + OFF_MBAR + (t & 1) * 8, TILE_BYTES);
            BULK_G2S(sb + buf, g_cbt + (size_t)(t + 2) * TILE_BYTES,
                     TILE_BYTES, sb + OFF_MBAR + (t & 1) * 8);
        }
    }

    // ---- merge top-4 across the 4 lanes sharing each row ----
    #pragma unroll
    for (int off = 1; off < 4; off <<= 1) {
        float ov[4]; int oi[4];
        #pragma unroll
        for (int s = 0; s < 4; s++) {
            ov[s] = __shfl_xor_sync(0xFFFFFFFFu, bvA[s], off, 4);
            oi[s] = __shfl_xor_sync(0xFFFFFFFFu, biA[s], off, 4);
        }
        #pragma unroll
        for (int s = 0; s < 4; s++) ins4(bvA, biA, ov[s], oi[s]);
        #pragma unroll
        for (int s = 0; s < 4; s++) {
            ov[s] = __shfl_xor_sync(0xFFFFFFFFu, bvB[s], off, 4);
            oi[s] = __shfl_xor_sync(0xFFFFFFFFu, biB[s], off, 4);
        }
        #pragma unroll
        for (int s = 0; s < 4; s++) ins4(bvB, biB, ov[s], oi[s]);
    }
    if ((lane & 3) == 0) {
        g_cand[R0 + rowA]     = make_int4(biA[0], biA[1], biA[2], biA[3]);
        g_cand[R0 + rowA + 8] = make_int4(biB[0], biB[1], biB[2], biB[3]);
    }
}

// ---------------- rescore: exact fp32 decision among top-4 + per-block loss ----------------
__global__ void vq_rescore(const float* __restrict__ z, const float* __restrict__ cb,
                           float* __restrict__ out_zq, float* __restrict__ out_idx_f,
                           int writeIdx, int N)
{
    __shared__ double sred[8];
    int wIn = threadIdx.x >> 5;
    int gw = blockIdx.x * 8 + wIn;
    int lane = threadIdx.x & 31;

    double ls = 0.0;
    if (gw < N) {
        int4 cand = g_cand[gw];
        int ci[4] = {cand.x, cand.y, cand.z, cand.w};
        float zn = g_zn[gw];

        const float4* zr = (const float4*)(z + (size_t)gw * D_);
        float4 za = zr[lane * 2], zb = zr[lane * 2 + 1];

        float4 ea[4], eb[4];
        float dot[4];
        #pragma unroll
        for (int q = 0; q < 4; q++) {
            const float4* ep = (const float4*)(cb + (size_t)ci[q] * D_);
            ea[q] = ep[lane * 2]; eb[q] = ep[lane * 2 + 1];
            dot[q] = za.x * ea[q].x + za.y * ea[q].y + za.z * ea[q].z + za.w * ea[q].w
                   + zb.x * eb[q].x + zb.y * eb[q].y + zb.z * eb[q].z + zb.w * eb[q].w;
        }
        #pragma unroll
        for (int o = 16; o; o >>= 1)
            #pragma unroll
            for (int q = 0; q < 4; q++)
                dot[q] += __shfl_xor_sync(0xFFFFFFFFu, dot[q], o);

        float bd = __int_as_float(0x7f800000);
        int   bi = 0x7fffffff, bq = 0;
        #pragma unroll
        for (int q = 0; q < 4; q++) {
            float dist = __fmaf_rn(-2.0f, dot[q], __fadd_rn(zn, g_enorm[ci[q]]));
            if (dist < bd || (dist == bd && ci[q] < bi)) { bd = dist; bi = ci[q]; bq = q; }
        }

        float4 wa = ea[bq], wb = eb[bq];
        float4* outr = (float4*)(out_zq + (size_t)gw * D_);
        outr[lane * 2]     = wa;
        outr[lane * 2 + 1] = wb;

        double dx;
        dx = (double)wa.x - za.x; ls += dx * dx;
        dx = (double)wa.y - za.y; ls += dx * dx;
        dx = (double)wa.z - za.z; ls += dx * dx;
        dx = (double)wa.w - za.w; ls += dx * dx;
        dx = (double)wb.x - zb.x; ls += dx * dx;
        dx = (double)wb.y - zb.y; ls += dx * dx;
        dx = (double)wb.z - zb.z; ls += dx * dx;
        dx = (double)wb.w - zb.w; ls += dx * dx;
        for (int o = 16; o; o >>= 1) ls += __shfl_xor_sync(0xFFFFFFFFu, ls, o);
        if (lane == 0 && writeIdx) out_idx_f[gw] = (float)bi;
    }
    if (lane == 0) sred[wIn] = ls;
    __syncthreads();
    if (threadIdx.x == 0) {
        double s = 0.0;
        #pragma unroll
        for (int w = 0; w < 8; w++) s += sred[w];
        g_partial[blockIdx.x] = s;
    }
}

// ---------------- deterministic loss reduction ----------------
__global__ void vq_loss(float* out_loss, int nPart, long long nElem) {
    __shared__ double s[256];
    double a0 = 0.0, a1 = 0.0, a2 = 0.0, a3 = 0.0;
    for (int i = threadIdx.x * 4; i < nPart; i += 1024) {
        a0 += g_partial[i]; a1 += g_partial[i + 1];
        a2 += g_partial[i + 2]; a3 += g_partial[i + 3];
    }
    s[threadIdx.x] = (a0 + a1) + (a2 + a3);
    __syncthreads();
    #pragma unroll
    for (int k = 128; k > 0; k >>= 1) {
        if (threadIdx.x < k) s[threadIdx.x] += s[threadIdx.x + k];
        __syncthreads();
    }
    if (threadIdx.x == 0)
        *out_loss = (float)(0.25 * s[0] / (double)nElem);
}

extern "C" void kernel_launch(void* const* d_in, const int* in_sizes, int n_in,
                              void* d_out, int out_size)
{
    const float* z  = (const float*)d_in[0];
    const float* cb = (const float*)d_in[1];
    const int N = in_sizes[0] / D_;
    const int K = in_sizes[1] / D_;

    float* out = (float*)d_out;
    const long long zq = (long long)N * D_;
    float* out_idx = nullptr;
    float* out_loss = nullptr;
    int writeIdx = 0;
    long long osz = (long long)out_size;
    if (osz >= zq + N) { out_idx = out + zq; writeIdx = 1; }
    if (osz >= zq + N + 1) out_loss = out + zq + N;
    else if (osz == zq + 1) out_loss = out + zq;

    cudaFuncSetAttribute(vq_tc, cudaFuncAttributeMaxDynamicSharedMemorySize, SMEM_TOTAL);

    vq_prep<<<(K + 7) / 8, 256>>>(cb, K);
    vq_tc<<<N / MROWS, THREADS, SMEM_TOTAL>>>(z, K);
    vq_rescore<<<N / 8, 256>>>(z, cb, out, out_idx, writeIdx, N);
    if (out_loss) vq_loss<<<1, 256>>>(out_loss, N / 8, (long long)N * D_);
}